// round 5
// baseline (speedup 1.0000x reference)
#include <cuda_runtime.h>
#include <cuda_bf16.h>
#include <math_constants.h>
#include <cstdint>

// ---------------- problem constants ----------------
#define BATCH_B   4
#define NB        4096
#define NPTS      (BATCH_B * NB)       // 16384
#define MBQ       1024                 // centroids per cloud
#define MTOT      (BATCH_B * MBQ)      // 4096
#define DIN       64
#define KNB       64
#define H1        128
#define H2        128
#define H3        256
#define LDA       136                  // padded row stride (bf16 elems), 272B

#define POS_OFF      ((size_t)MTOT * H3)
#define POS_ELEMS    ((size_t)MTOT * 3)
#define BATCH_OFF    (POS_OFF + POS_ELEMS)
#define BATCH_ELEMS  ((size_t)MTOT)

#define NPREP 144                       // conv blocks that also do prep
#define SELFLAG 0x80000000u

// ---------------- device scratch ----------------
__device__ unsigned g_selpub[MTOT];            // published FPS selections (flag|idx)
__device__ int      g_prep_done;               // prep barrier counter
__device__ float    g_xw1[(size_t)NPTS * H1];  // x @ W1[:64] + b1
__device__ __align__(16) __nv_bfloat16 g_w2t_hi[H2 * LDA];
__device__ __align__(16) __nv_bfloat16 g_w2t_lo[H2 * LDA];
__device__ __align__(16) __nv_bfloat16 g_w3t_hi[H3 * LDA];
__device__ __align__(16) __nv_bfloat16 g_w3t_lo[H3 * LDA];

// exact mul-then-add (match XLA square->sum, no FMA contraction)
__device__ __forceinline__ float d2_exact(float dx, float dy, float dz) {
    return __fadd_rn(__fadd_rn(__fmul_rn(dx, dx), __fmul_rn(dy, dy)), __fmul_rn(dz, dz));
}

// ---- packed f32x2 helpers (FPS) ----
__device__ __forceinline__ unsigned long long pack2(float lo, float hi) {
    unsigned long long r;
    asm("mov.b64 %0, {%1, %2};" : "=l"(r) : "f"(lo), "f"(hi));
    return r;
}
__device__ __forceinline__ void unpack2(unsigned long long v, float& lo, float& hi) {
    asm("mov.b64 {%0, %1}, %2;" : "=f"(lo), "=f"(hi) : "l"(v));
}
__device__ __forceinline__ unsigned long long add2(unsigned long long a, unsigned long long b) {
    unsigned long long r;
    asm("add.rn.f32x2 %0, %1, %2;" : "=l"(r) : "l"(a), "l"(b));
    return r;
}
__device__ __forceinline__ unsigned long long mul2(unsigned long long a, unsigned long long b) {
    unsigned long long r;
    asm("mul.rn.f32x2 %0, %1, %2;" : "=l"(r) : "l"(a), "l"(b));
    return r;
}

// ---- sync helpers ----
__device__ __forceinline__ unsigned ld_acq(const unsigned* p) {
    unsigned v;
    asm volatile("ld.global.acquire.gpu.b32 %0, [%1];" : "=r"(v) : "l"(p));
    return v;
}
__device__ __forceinline__ void st_rel(unsigned* p, unsigned v) {
    asm volatile("st.global.release.gpu.b32 [%0], %1;" :: "l"(p), "r"(v));
}

// ---- mma/ldmatrix helpers (portable PTX) ----
__device__ __forceinline__ uint32_t smem_u32(const void* p) {
    uint32_t a;
    asm("{ .reg .u64 t; cvta.to.shared.u64 t, %1; cvt.u32.u64 %0, t; }" : "=r"(a) : "l"(p));
    return a;
}
__device__ __forceinline__ void ldmat4(uint32_t* r, uint32_t a) {
    asm volatile("ldmatrix.sync.aligned.m8n8.x4.shared.b16 {%0,%1,%2,%3}, [%4];"
                 : "=r"(r[0]), "=r"(r[1]), "=r"(r[2]), "=r"(r[3]) : "r"(a));
}
__device__ __forceinline__ void mma16816(float* d, const uint32_t* a, const uint32_t* b) {
    asm volatile(
        "mma.sync.aligned.m16n8k16.row.col.f32.bf16.bf16.f32 "
        "{%0,%1,%2,%3}, {%4,%5,%6,%7}, {%8,%9}, {%0,%1,%2,%3};"
        : "+f"(d[0]), "+f"(d[1]), "+f"(d[2]), "+f"(d[3])
        : "r"(a[0]), "r"(a[1]), "r"(a[2]), "r"(a[3]), "r"(b[0]), "r"(b[1]));
}
__device__ __forceinline__ void split_bf16(float v, __nv_bfloat16& hi, __nv_bfloat16& lo) {
    hi = __float2bfloat16_rn(v);
    lo = __float2bfloat16_rn(v - __bfloat162float(hi));
}
__device__ __forceinline__ uint32_t packbf(__nv_bfloat16 a, __nv_bfloat16 b) {
    __nv_bfloat162 t;
    t.x = a; t.y = b;
    return *(uint32_t*)&t;
}

// ---------------- smem layout (conv path) ----------------
#define OFF_A_HI   0
#define OFF_A_LO   34816
#define OFF_B_HI   69632
#define OFF_B_LO   139264
#define OFF_OMAX   208896
#define OFF_W1R    210944
#define OFF_NBR    212480   // int snbr[2][64]
#define OFF_SCNT   212992   // int scnt[2]
#define OFF_SQP    213000   // float sqp[2][3]
#define MEGA_SMEM  213120

// ================= clear kernel (per-launch reset, graph-safe) =============
__global__ __launch_bounds__(256)
void clear_kernel() {
    const int i = blockIdx.x * 256 + threadIdx.x;
    if (i < MTOT) g_selpub[i] = 0u;
    if (i == 0) g_prep_done = 0;
}

// ================= mega kernel: FPS (blocks 0-3) + conv (blocks 4..) =======
#define FPT 16
__global__ __launch_bounds__(256, 1)
void mega_kernel(const float* __restrict__ pos, const float* __restrict__ x,
                 const float* __restrict__ W1, const float* __restrict__ b1,
                 const float* __restrict__ W2, const float* __restrict__ b2,
                 const float* __restrict__ W3, const float* __restrict__ b3,
                 float* __restrict__ out, long long out_size) {
    extern __shared__ char sm[];
    const int tid  = threadIdx.x;
    const int warp = tid >> 5;
    const int lane = tid & 31;

    if (blockIdx.x < 4) {
        // ========================= FPS =========================
        const int b = blockIdx.x;
        const float* p = pos + (size_t)b * NB * 3;
        float* spx = (float*)sm;
        float* spy = spx + NB;
        float* spz = spy + NB;
        unsigned long long* sled = (unsigned long long*)(spz + NB);  // [2][8]

        unsigned long long ppx[FPT / 2], ppy[FPT / 2], ppz[FPT / 2];
        float dd[FPT];
        {
            float tx[FPT], ty[FPT], tz[FPT];
#pragma unroll
            for (int u = 0; u < FPT; u++) {
                const int j = u * 256 + tid;
                tx[u] = p[j * 3 + 0];
                ty[u] = p[j * 3 + 1];
                tz[u] = p[j * 3 + 2];
                spx[j] = tx[u]; spy[j] = ty[u]; spz[j] = tz[u];
                dd[u] = CUDART_INF_F;
            }
#pragma unroll
            for (int q = 0; q < FPT / 2; q++) {
                ppx[q] = pack2(tx[2 * q], tx[2 * q + 1]);
                ppy[q] = pack2(ty[2 * q], ty[2 * q + 1]);
                ppz[q] = pack2(tz[2 * q], tz[2 * q + 1]);
            }
        }
        if (tid == 0) st_rel(&g_selpub[b * MBQ], SELFLAG | 0u);   // sel[0] = 0
        __syncthreads();

        float cx = spx[0], cy = spy[0], cz = spz[0];

        for (int k = 1; k < MBQ; k++) {
            const unsigned long long ncx = pack2(-cx, -cx);
            const unsigned long long ncy = pack2(-cy, -cy);
            const unsigned long long ncz = pack2(-cz, -cz);
#pragma unroll
            for (int q = 0; q < FPT / 2; q++) {
                unsigned long long dx = add2(ppx[q], ncx);
                unsigned long long dy = add2(ppy[q], ncy);
                unsigned long long dz = add2(ppz[q], ncz);
                unsigned long long s  = add2(add2(mul2(dx, dx), mul2(dy, dy)), mul2(dz, dz));
                float d0, d1;
                unpack2(s, d0, d1);
                dd[2 * q]     = fminf(dd[2 * q], d0);
                dd[2 * q + 1] = fminf(dd[2 * q + 1], d1);
            }
            // local argmax tree, keep-left on tie (= smallest index)
            float tv[FPT]; int tu[FPT];
#pragma unroll
            for (int u = 0; u < FPT; u++) { tv[u] = dd[u]; tu[u] = u; }
#pragma unroll
            for (int step = 1; step < FPT; step <<= 1) {
#pragma unroll
                for (int u = 0; u < FPT; u += 2 * step) {
                    const bool take = tv[u + step] > tv[u];
                    tv[u] = take ? tv[u + step] : tv[u];
                    tu[u] = take ? tu[u + step] : tu[u];
                }
            }
            const int myidx = tu[0] * 256 + tid;
            const unsigned vb = __float_as_uint(tv[0]);   // d2 >= 0: uint order == float order
            const unsigned mx = __reduce_max_sync(0xffffffffu, vb);
            const unsigned cand = (vb == mx) ? (unsigned)myidx : 0xffffffffu;
            const unsigned imin = __reduce_min_sync(0xffffffffu, cand);

            const int par = k & 1;
            if (lane == 0)
                sled[par * 8 + warp] = ((unsigned long long)mx << 32) | (unsigned)(NB - 1 - imin);
            __syncthreads();

            unsigned long long m = sled[par * 8 + 0];
#pragma unroll
            for (int w = 1; w < 8; w++) {
                unsigned long long o = sled[par * 8 + w];
                if (o > m) m = o;
            }
            const int widx = NB - 1 - (int)(unsigned)(m & 0xffffffffu);
            if (tid == 0) st_rel(&g_selpub[b * MBQ + k], SELFLAG | (unsigned)widx);
            cx = spx[widx]; cy = spy[widx]; cz = spz[widx];
        }
        return;
    }

    // ========================= CONV =========================
    const int p     = blockIdx.x - 4;          // 0..2047
    const int cloud = p & 3;
    const int kk    = p >> 2;
    const int c0    = cloud * MBQ + kk * 2;    // 2 centroids per block
    const int gp    = cloud * NB;

    const uint32_t sb = smem_u32(sm);
    __nv_bfloat16* Ahi = (__nv_bfloat16*)(sm + OFF_A_HI);
    __nv_bfloat16* Alo = (__nv_bfloat16*)(sm + OFF_A_LO);
    int*   omax = (int*)(sm + OFF_OMAX);
    float* w1r  = (float*)(sm + OFF_W1R);
    int*   snbr = (int*)(sm + OFF_NBR);        // [2][64]
    int*   scnt = (int*)(sm + OFF_SCNT);
    float* sqp  = (float*)(sm + OFF_SQP);      // [2][3]

    // ---- step A: prep work for blocks p < NPREP (xw1 + weight split) ----
    if (p < NPREP) {
        const int t  = tid & 127;
        const int rh = tid >> 7;
        for (int rp = p; rp < NPTS / 2; rp += NPREP) {
            const int row = rp * 2 + rh;
            float acc = __ldg(&b1[t]);
            const float* xr = x + (size_t)row * DIN;
#pragma unroll 8
            for (int i = 0; i < DIN; i++)
                acc = fmaf(__ldg(&xr[i]), __ldg(&W1[i * H1 + t]), acc);
            g_xw1[(size_t)row * H1 + t] = acc;
        }
        for (int idx = p * 256 + tid; idx < H2 * H1 + H3 * H2; idx += NPREP * 256) {
            if (idx < H2 * H1) {
                const int n = idx & 127, k = idx >> 7;
                __nv_bfloat16 hi, lo;
                split_bf16(__ldg(&W2[k * H2 + n]), hi, lo);
                g_w2t_hi[n * LDA + k] = hi;
                g_w2t_lo[n * LDA + k] = lo;
            } else {
                const int r = idx - H2 * H1;
                const int n = r & 255, k = r >> 8;
                __nv_bfloat16 hi, lo;
                split_bf16(__ldg(&W3[k * H3 + n]), hi, lo);
                g_w3t_hi[n * LDA + k] = hi;
                g_w3t_lo[n * LDA + k] = lo;
            }
        }
        __threadfence();
        __syncthreads();
        if (tid == 0) atomicAdd(&g_prep_done, 1);
    }

    // ---- init smem, wait for prep barrier ----
    for (int i = tid; i < 512; i += 256) omax[i] = 0;
    if (tid < 128) {
        w1r[tid]       = __ldg(&W1[64 * H1 + tid]);
        w1r[128 + tid] = __ldg(&W1[65 * H1 + tid]);
        w1r[256 + tid] = __ldg(&W1[66 * H1 + tid]);
    }
    if (tid == 0) {
        while (ld_acq((const unsigned*)&g_prep_done) < NPREP) __nanosleep(128);
    }
    __syncthreads();
    __threadfence();   // order: barrier observed -> g_xw1 / weight reads below

    // ---- step C: warps 0-1 do per-centroid radius; warps 2-7 copy W2T ----
    if (warp < 2) {
        const int ci = c0 + warp;
        unsigned v = 0;
        if (lane == 0) {
            while (((v = ld_acq(&g_selpub[ci])) & SELFLAG) == 0u) __nanosleep(64);
        }
        v = __shfl_sync(0xffffffffu, v, 0);
        const int sel = (int)(v & 0xFFFFu);
        const float* pp = pos + (size_t)cloud * NB * 3;
        const float qx = pp[sel * 3 + 0];
        const float qy = pp[sel * 3 + 1];
        const float qz = pp[sel * 3 + 2];
        if (lane == 0) {
            sqp[warp * 3 + 0] = qx;
            sqp[warp * 3 + 1] = qy;
            sqp[warp * 3 + 2] = qz;
            if (out_size >= (long long)(POS_OFF + POS_ELEMS)) {
                out[POS_OFF + (size_t)ci * 3 + 0] = qx;
                out[POS_OFF + (size_t)ci * 3 + 1] = qy;
                out[POS_OFF + (size_t)ci * 3 + 2] = qz;
            }
            if (out_size >= (long long)(BATCH_OFF + BATCH_ELEMS)) {
                out[BATCH_OFF + ci] = (float)cloud;
            }
        }
        const float R2 = 0.04f;   // f32(0.2*0.2)
        int cnt = 0;
        for (int base = 0; base < NB; base += 32) {
            const int j = base + lane;
            float d2 = d2_exact(pp[j * 3 + 0] - qx, pp[j * 3 + 1] - qy, pp[j * 3 + 2] - qz);
            const bool in = (d2 <= R2);
            const unsigned msk = __ballot_sync(0xffffffffu, in);
            if (in) {
                int r = cnt + __popc(msk & ((1u << lane) - 1u));
                if (r < KNB) snbr[warp * KNB + r] = j;
            }
            cnt += __popc(msk);
            if (cnt >= KNB) break;
        }
        if (lane == 0) scnt[warp] = cnt < KNB ? cnt : KNB;
    } else {
        // copy W2T hi/lo images (each warp copies a slice)
        const float4* s0 = (const float4*)g_w2t_hi;
        const float4* s1 = (const float4*)g_w2t_lo;
        float4* d0 = (float4*)(sm + OFF_B_HI);
        float4* d1 = (float4*)(sm + OFF_B_LO);
        const int tot = (H2 * LDA * 2) / 16;   // 2176 float4 per image
        for (int i = (tid - 64); i < tot; i += 192) { d0[i] = s0[i]; d1[i] = s1[i]; }
    }
    __syncthreads();

    // ---- phase 1: build A = h1 split (hi/lo bf16) ----
    {
        const int m    = tid >> 1;
        const int hf   = tid & 1;
        const int half = m >> 6;
        const int slot = m & 63;
        const int cnt  = scnt[half];
        const bool valid = slot < cnt;
        const int j = valid ? (snbr[half * KNB + slot] + gp) : gp;
        const float rx = __ldg(&pos[j * 3 + 0]) - sqp[half * 3 + 0];
        const float ry = __ldg(&pos[j * 3 + 1]) - sqp[half * 3 + 1];
        const float rz = __ldg(&pos[j * 3 + 2]) - sqp[half * 3 + 2];
        const float* xrow = g_xw1 + (size_t)j * H1;
#pragma unroll 4
        for (int c4 = hf * 64; c4 < hf * 64 + 64; c4 += 4) {
            const float4 xv = __ldg((const float4*)(xrow + c4));
            const float xe[4] = {xv.x, xv.y, xv.z, xv.w};
            __nv_bfloat16 hi[4], lo[4];
#pragma unroll
            for (int e = 0; e < 4; e++) {
                const int t = c4 + e;
                float v = xe[e];
                v = fmaf(rx, w1r[t], v);
                v = fmaf(ry, w1r[128 + t], v);
                v = fmaf(rz, w1r[256 + t], v);
                v = fmaxf(v, 0.0f);
                if (!valid) v = 0.0f;
                split_bf16(v, hi[e], lo[e]);
            }
            *(uint32_t*)(Ahi + m * LDA + c4)     = packbf(hi[0], hi[1]);
            *(uint32_t*)(Ahi + m * LDA + c4 + 2) = packbf(hi[2], hi[3]);
            *(uint32_t*)(Alo + m * LDA + c4)     = packbf(lo[0], lo[1]);
            *(uint32_t*)(Alo + m * LDA + c4 + 2) = packbf(lo[2], lo[3]);
        }
    }
    __syncthreads();

    const uint32_t aAhi = sb + OFF_A_HI, aAlo = sb + OFF_A_LO;
    const uint32_t aBhi = sb + OFF_B_HI, aBlo = sb + OFF_B_LO;

    // ---- GEMM1: h2_pre[128x128] = A @ W2 (bf16x3) ----
    float d1r[2][8][4] = {};
    {
        const int mw = (warp & 3) * 32;
        const int nw = (warp >> 2) * 64;
        for (int ks = 0; ks < 8; ks++) {
            const uint32_t colo = (uint32_t)(ks * 16 + (lane >> 4) * 8) * 2;
            uint32_t ah[2][4], al[2][4];
#pragma unroll
            for (int mf = 0; mf < 2; mf++) {
                const uint32_t ro = (uint32_t)(mw + mf * 16 + (lane & 15)) * (LDA * 2);
                ldmat4(ah[mf], aAhi + ro + colo);
                ldmat4(al[mf], aAlo + ro + colo);
            }
            uint32_t bh[8][2], bl[8][2];
#pragma unroll
            for (int np = 0; np < 4; np++) {
                const uint32_t ro = (uint32_t)(nw + np * 16 + (lane & 15)) * (LDA * 2);
                uint32_t r[4];
                ldmat4(r, aBhi + ro + colo);
                bh[2 * np][0] = r[0]; bh[2 * np][1] = r[2];
                bh[2 * np + 1][0] = r[1]; bh[2 * np + 1][1] = r[3];
                ldmat4(r, aBlo + ro + colo);
                bl[2 * np][0] = r[0]; bl[2 * np][1] = r[2];
                bl[2 * np + 1][0] = r[1]; bl[2 * np + 1][1] = r[3];
            }
#pragma unroll
            for (int mf = 0; mf < 2; mf++)
#pragma unroll
                for (int nf = 0; nf < 8; nf++) {
                    mma16816(d1r[mf][nf], ah[mf], bh[nf]);
                    mma16816(d1r[mf][nf], ah[mf], bl[nf]);
                    mma16816(d1r[mf][nf], al[mf], bh[nf]);
                }
        }
    }
    __syncthreads();

    // ---- epilogue 1: h2 = relu(D1 + b2) -> split back into A; copy W3T ----
    {
        const int mw = (warp & 3) * 32;
        const int nw = (warp >> 2) * 64;
        const int g  = lane >> 2;
        const int tg = lane & 3;
#pragma unroll
        for (int mf = 0; mf < 2; mf++) {
            const int row0 = mw + mf * 16 + g;
#pragma unroll
            for (int nf = 0; nf < 8; nf++) {
                const int col = nw + nf * 8 + tg * 2;
                const float bb0 = __ldg(&b2[col]);
                const float bb1 = __ldg(&b2[col + 1]);
                const float v00 = fmaxf(d1r[mf][nf][0] + bb0, 0.0f);
                const float v01 = fmaxf(d1r[mf][nf][1] + bb1, 0.0f);
                const float v10 = fmaxf(d1r[mf][nf][2] + bb0, 0.0f);
                const float v11 = fmaxf(d1r[mf][nf][3] + bb1, 0.0f);
                __nv_bfloat16 h0, l0, h1b, l1b, h2b, l2b, h3b, l3b;
                split_bf16(v00, h0, l0);
                split_bf16(v01, h1b, l1b);
                split_bf16(v10, h2b, l2b);
                split_bf16(v11, h3b, l3b);
                *(uint32_t*)(Ahi + row0 * LDA + col)       = packbf(h0, h1b);
                *(uint32_t*)(Alo + row0 * LDA + col)       = packbf(l0, l1b);
                *(uint32_t*)(Ahi + (row0 + 8) * LDA + col) = packbf(h2b, h3b);
                *(uint32_t*)(Alo + (row0 + 8) * LDA + col) = packbf(l2b, l3b);
            }
        }
    }
    {
        const float4* s0 = (const float4*)g_w3t_hi;
        const float4* s1 = (const float4*)g_w3t_lo;
        float4* d0 = (float4*)(sm + OFF_B_HI);
        float4* d1 = (float4*)(sm + OFF_B_LO);
        for (int i = tid; i < (H3 * LDA * 2) / 16; i += 256) { d0[i] = s0[i]; d1[i] = s1[i]; }
    }
    __syncthreads();

    // ---- GEMM2 + fused masked max epilogue ----
    const int cnt0 = scnt[0];
    const int cnt1 = scnt[1];
    const int g  = lane >> 2;
    const int tg = lane & 3;
#pragma unroll
    for (int rep = 0; rep < 2; rep++) {
        const int T  = warp + 8 * rep;
        const int m0 = (T & 3) * 32;
        const int n0 = (T >> 2) * 64;
        float d2r[2][8][4] = {};
        for (int ks = 0; ks < 8; ks++) {
            const uint32_t colo = (uint32_t)(ks * 16 + (lane >> 4) * 8) * 2;
            uint32_t ah[2][4], al[2][4];
#pragma unroll
            for (int mf = 0; mf < 2; mf++) {
                const uint32_t ro = (uint32_t)(m0 + mf * 16 + (lane & 15)) * (LDA * 2);
                ldmat4(ah[mf], aAhi + ro + colo);
                ldmat4(al[mf], aAlo + ro + colo);
            }
            uint32_t bh[8][2], bl[8][2];
#pragma unroll
            for (int np = 0; np < 4; np++) {
                const uint32_t ro = (uint32_t)(n0 + np * 16 + (lane & 15)) * (LDA * 2);
                uint32_t r[4];
                ldmat4(r, aBhi + ro + colo);
                bh[2 * np][0] = r[0]; bh[2 * np][1] = r[2];
                bh[2 * np + 1][0] = r[1]; bh[2 * np + 1][1] = r[3];
                ldmat4(r, aBlo + ro + colo);
                bl[2 * np][0] = r[0]; bl[2 * np][1] = r[2];
                bl[2 * np + 1][0] = r[1]; bl[2 * np + 1][1] = r[3];
            }
#pragma unroll
            for (int mf = 0; mf < 2; mf++)
#pragma unroll
                for (int nf = 0; nf < 8; nf++) {
                    mma16816(d2r[mf][nf], ah[mf], bh[nf]);
                    mma16816(d2r[mf][nf], ah[mf], bl[nf]);
                    mma16816(d2r[mf][nf], al[mf], bh[nf]);
                }
        }
        const int count = (m0 >= 64) ? cnt1 : cnt0;
        const int cbase = (m0 >= 64) ? 256 : 0;
        const int rr = (m0 & 32) + g;
        const bool v0 = rr < count;
        const bool v1 = rr + 8 < count;
        const bool v2 = rr + 16 < count;
        const bool v3 = rr + 24 < count;
#pragma unroll
        for (int nf = 0; nf < 8; nf++) {
            const int col = n0 + nf * 8 + tg * 2;
            const float bb0 = __ldg(&b3[col]);
            const float bb1 = __ldg(&b3[col + 1]);
            float mx0 = 0.0f, mx1 = 0.0f;
            if (v0) { mx0 = fmaxf(mx0, d2r[0][nf][0] + bb0); mx1 = fmaxf(mx1, d2r[0][nf][1] + bb1); }
            if (v1) { mx0 = fmaxf(mx0, d2r[0][nf][2] + bb0); mx1 = fmaxf(mx1, d2r[0][nf][3] + bb1); }
            if (v2) { mx0 = fmaxf(mx0, d2r[1][nf][0] + bb0); mx1 = fmaxf(mx1, d2r[1][nf][1] + bb1); }
            if (v3) { mx0 = fmaxf(mx0, d2r[1][nf][2] + bb0); mx1 = fmaxf(mx1, d2r[1][nf][3] + bb1); }
#pragma unroll
            for (int off = 4; off <= 16; off <<= 1) {
                mx0 = fmaxf(mx0, __shfl_xor_sync(0xffffffffu, mx0, off));
                mx1 = fmaxf(mx1, __shfl_xor_sync(0xffffffffu, mx1, off));
            }
            if (lane < 4) {
                atomicMax(&omax[cbase + col],     __float_as_int(mx0));
                atomicMax(&omax[cbase + col + 1], __float_as_int(mx1));
            }
        }
    }
    __syncthreads();

    for (int i = tid; i < 512; i += 256)
        out[(size_t)(c0 + (i >> 8)) * H3 + (i & 255)] = __int_as_float(omax[i]);
}

// ================= launch =================
extern "C" void kernel_launch(void* const* d_in, const int* in_sizes, int n_in,
                              void* d_out, int out_size) {
    const float* x   = (const float*)d_in[0];
    const float* pos = (const float*)d_in[1];
    // d_in[2] = batch (int32), unused: clouds contiguous & equal-sized
    const float* W1  = (const float*)d_in[3];
    const float* b1  = (const float*)d_in[4];
    const float* W2  = (const float*)d_in[5];
    const float* b2  = (const float*)d_in[6];
    const float* W3  = (const float*)d_in[7];
    const float* b3  = (const float*)d_in[8];
    float* out = (float*)d_out;

    cudaFuncSetAttribute(mega_kernel, cudaFuncAttributeMaxDynamicSharedMemorySize, MEGA_SMEM);

    clear_kernel<<<(MTOT + 255) / 256, 256>>>();
    mega_kernel<<<4 + MTOT / 2, 256, MEGA_SMEM>>>(pos, x, W1, b1, W2, b2, W3, b3,
                                                  out, (long long)out_size);
}

// round 6
// speedup vs baseline: 1.0816x; 1.0816x over previous
#include <cuda_runtime.h>
#include <cuda_bf16.h>
#include <math_constants.h>
#include <cstdint>

// ---------------- problem constants ----------------
#define BATCH_B   4
#define NB        4096
#define NPTS      (BATCH_B * NB)       // 16384
#define MBQ       1024                 // centroids per cloud
#define MTOT      (BATCH_B * MBQ)      // 4096
#define DIN       64
#define KNB       64
#define H1        128
#define H2        128
#define H3        256
#define LDA       136                  // padded row stride (bf16 elems), 272B

#define POS_OFF      ((size_t)MTOT * H3)
#define POS_ELEMS    ((size_t)MTOT * 3)
#define BATCH_OFF    (POS_OFF + POS_ELEMS)
#define BATCH_ELEMS  ((size_t)MTOT)

// ---------------- device scratch ----------------
__device__ int   g_sel[MTOT];
__device__ float g_qpos[MTOT * 3];
__device__ int   g_nbr[MTOT * KNB];
__device__ int   g_cnt[MTOT];
__device__ float g_xw1[(size_t)NPTS * H1];
__device__ __align__(16) __nv_bfloat16 g_w2t_hi[H2 * LDA];
__device__ __align__(16) __nv_bfloat16 g_w2t_lo[H2 * LDA];
__device__ __align__(16) __nv_bfloat16 g_w3t_hi[H3 * LDA];
__device__ __align__(16) __nv_bfloat16 g_w3t_lo[H3 * LDA];

// exact mul-then-add (match XLA square->sum, no FMA contraction)
__device__ __forceinline__ float d2_exact(float dx, float dy, float dz) {
    return __fadd_rn(__fadd_rn(__fmul_rn(dx, dx), __fmul_rn(dy, dy)), __fmul_rn(dz, dz));
}

// ---- packed f32x2 helpers (FPS) ----
__device__ __forceinline__ unsigned long long pack2(float lo, float hi) {
    unsigned long long r;
    asm("mov.b64 %0, {%1, %2};" : "=l"(r) : "f"(lo), "f"(hi));
    return r;
}
__device__ __forceinline__ void unpack2(unsigned long long v, float& lo, float& hi) {
    asm("mov.b64 {%0, %1}, %2;" : "=f"(lo), "=f"(hi) : "l"(v));
}
__device__ __forceinline__ unsigned long long add2(unsigned long long a, unsigned long long b) {
    unsigned long long r;
    asm("add.rn.f32x2 %0, %1, %2;" : "=l"(r) : "l"(a), "l"(b));
    return r;
}
__device__ __forceinline__ unsigned long long mul2(unsigned long long a, unsigned long long b) {
    unsigned long long r;
    asm("mul.rn.f32x2 %0, %1, %2;" : "=l"(r) : "l"(a), "l"(b));
    return r;
}

// ---- mma/ldmatrix helpers (portable PTX) ----
__device__ __forceinline__ uint32_t smem_u32(const void* p) {
    uint32_t a;
    asm("{ .reg .u64 t; cvta.to.shared.u64 t, %1; cvt.u32.u64 %0, t; }" : "=r"(a) : "l"(p));
    return a;
}
__device__ __forceinline__ void ldmat4(uint32_t* r, uint32_t a) {
    asm volatile("ldmatrix.sync.aligned.m8n8.x4.shared.b16 {%0,%1,%2,%3}, [%4];"
                 : "=r"(r[0]), "=r"(r[1]), "=r"(r[2]), "=r"(r[3]) : "r"(a));
}
__device__ __forceinline__ void mma16816(float* d, const uint32_t* a, const uint32_t* b) {
    asm volatile(
        "mma.sync.aligned.m16n8k16.row.col.f32.bf16.bf16.f32 "
        "{%0,%1,%2,%3}, {%4,%5,%6,%7}, {%8,%9}, {%0,%1,%2,%3};"
        : "+f"(d[0]), "+f"(d[1]), "+f"(d[2]), "+f"(d[3])
        : "r"(a[0]), "r"(a[1]), "r"(a[2]), "r"(a[3]), "r"(b[0]), "r"(b[1]));
}
__device__ __forceinline__ void split_bf16(float v, __nv_bfloat16& hi, __nv_bfloat16& lo) {
    hi = __float2bfloat16_rn(v);
    lo = __float2bfloat16_rn(v - __bfloat162float(hi));
}
__device__ __forceinline__ uint32_t packbf(__nv_bfloat16 a, __nv_bfloat16 b) {
    __nv_bfloat162 t;
    t.x = a; t.y = b;
    return *(uint32_t*)&t;
}

// ================= 1) fused: FPS (blocks 0-3) + xw1/W-prep (blocks 4..147) ===
#define FPT 16
#define NPREP 144
__global__ __launch_bounds__(256, 1)
void fused_fps_prep(const float* __restrict__ pos, const float* __restrict__ x,
                    const float* __restrict__ W1, const float* __restrict__ b1,
                    const float* __restrict__ W2, const float* __restrict__ W3) {
    __shared__ float spx[NB], spy[NB], spz[NB];
    __shared__ unsigned long long sled[2][8];

    if (blockIdx.x < 4) {
        // ---------------- FPS ----------------
        const int b    = blockIdx.x;
        const int tid  = threadIdx.x;
        const int lane = tid & 31;
        const int warp = tid >> 5;
        const float* p = pos + (size_t)b * NB * 3;

        unsigned long long ppx[FPT / 2], ppy[FPT / 2], ppz[FPT / 2];
        float dd[FPT];
        {
            float tx[FPT], ty[FPT], tz[FPT];
#pragma unroll
            for (int u = 0; u < FPT; u++) {
                const int j = u * 256 + tid;
                tx[u] = p[j * 3 + 0];
                ty[u] = p[j * 3 + 1];
                tz[u] = p[j * 3 + 2];
                spx[j] = tx[u]; spy[j] = ty[u]; spz[j] = tz[u];
                dd[u] = CUDART_INF_F;
            }
#pragma unroll
            for (int q = 0; q < FPT / 2; q++) {
                ppx[q] = pack2(tx[2 * q], tx[2 * q + 1]);
                ppy[q] = pack2(ty[2 * q], ty[2 * q + 1]);
                ppz[q] = pack2(tz[2 * q], tz[2 * q + 1]);
            }
        }
        if (tid == 0) g_sel[b * MBQ] = 0;
        __syncthreads();

        float cx = spx[0], cy = spy[0], cz = spz[0];

        for (int k = 1; k < MBQ; k++) {
            const unsigned long long ncx = pack2(-cx, -cx);
            const unsigned long long ncy = pack2(-cy, -cy);
            const unsigned long long ncz = pack2(-cz, -cz);
#pragma unroll
            for (int q = 0; q < FPT / 2; q++) {
                unsigned long long dx = add2(ppx[q], ncx);
                unsigned long long dy = add2(ppy[q], ncy);
                unsigned long long dz = add2(ppz[q], ncz);
                unsigned long long s  = add2(add2(mul2(dx, dx), mul2(dy, dy)), mul2(dz, dz));
                float d0, d1;
                unpack2(s, d0, d1);
                dd[2 * q]     = fminf(dd[2 * q], d0);
                dd[2 * q + 1] = fminf(dd[2 * q + 1], d1);
            }
            // local argmax tree, keep-left on tie (= smallest index)
            float tv[FPT]; int tu[FPT];
#pragma unroll
            for (int u = 0; u < FPT; u++) { tv[u] = dd[u]; tu[u] = u; }
#pragma unroll
            for (int step = 1; step < FPT; step <<= 1) {
#pragma unroll
                for (int u = 0; u < FPT; u += 2 * step) {
                    const bool take = tv[u + step] > tv[u];
                    tv[u] = take ? tv[u + step] : tv[u];
                    tu[u] = take ? tu[u + step] : tu[u];
                }
            }
            const int myidx = tu[0] * 256 + tid;
            const unsigned vb = __float_as_uint(tv[0]);   // d2 >= 0: uint order == float order
            const unsigned mx = __reduce_max_sync(0xffffffffu, vb);
            const unsigned cand = (vb == mx) ? (unsigned)myidx : 0xffffffffu;
            const unsigned imin = __reduce_min_sync(0xffffffffu, cand);

            const int par = k & 1;
            if (lane == 0)
                sled[par][warp] = ((unsigned long long)mx << 32) | (unsigned)(NB - 1 - imin);
            __syncthreads();

            unsigned long long m = sled[par][0];
#pragma unroll
            for (int w = 1; w < 8; w++) {
                unsigned long long o = sled[par][w];
                if (o > m) m = o;
            }
            const int widx = NB - 1 - (int)(unsigned)(m & 0xffffffffu);
            if (tid == 0) g_sel[b * MBQ + k] = widx;
            cx = spx[widx]; cy = spy[widx]; cz = spz[widx];
        }
    } else {
        // ---------------- prep: xw1 + weight split/transpose ----------------
        const int pb  = blockIdx.x - 4;
        const int tid = threadIdx.x;
        const int t   = tid & 127;
        const int rh  = tid >> 7;

        for (int rp = pb; rp < NPTS / 2; rp += NPREP) {
            const int row = rp * 2 + rh;
            float acc = __ldg(&b1[t]);
            const float* xr = x + (size_t)row * DIN;
#pragma unroll 8
            for (int i = 0; i < DIN; i++)
                acc = fmaf(__ldg(&xr[i]), __ldg(&W1[i * H1 + t]), acc);
            g_xw1[(size_t)row * H1 + t] = acc;
        }

        for (int idx = pb * 256 + tid; idx < H2 * H1 + H3 * H2; idx += NPREP * 256) {
            if (idx < H2 * H1) {
                const int n = idx & 127, k = idx >> 7;
                __nv_bfloat16 hi, lo;
                split_bf16(__ldg(&W2[k * H2 + n]), hi, lo);
                g_w2t_hi[n * LDA + k] = hi;
                g_w2t_lo[n * LDA + k] = lo;
            } else {
                const int r = idx - H2 * H1;
                const int n = r & 255, k = r >> 8;
                __nv_bfloat16 hi, lo;
                split_bf16(__ldg(&W3[k * H3 + n]), hi, lo);
                g_w3t_hi[n * LDA + k] = hi;
                g_w3t_lo[n * LDA + k] = lo;
            }
        }
    }
}

// ================= 2) Radius search (first K in index order) =================
__global__ __launch_bounds__(256)
void radius_kernel(const float* __restrict__ pos, float* __restrict__ out, long long out_size) {
    const int warp = (blockIdx.x * blockDim.x + threadIdx.x) >> 5;
    const int lane = threadIdx.x & 31;
    if (warp >= MTOT) return;
    const int b  = warp >> 10;
    const float* p = pos + (size_t)b * NB * 3;

    const int selIdx = g_sel[warp];
    const float qx = p[selIdx * 3 + 0];
    const float qy = p[selIdx * 3 + 1];
    const float qz = p[selIdx * 3 + 2];

    if (lane == 0) {
        g_qpos[warp * 3 + 0] = qx;
        g_qpos[warp * 3 + 1] = qy;
        g_qpos[warp * 3 + 2] = qz;
        if (out_size >= (long long)(POS_OFF + POS_ELEMS)) {
            out[POS_OFF + (size_t)warp * 3 + 0] = qx;
            out[POS_OFF + (size_t)warp * 3 + 1] = qy;
            out[POS_OFF + (size_t)warp * 3 + 2] = qz;
        }
        if (out_size >= (long long)(BATCH_OFF + BATCH_ELEMS)) {
            out[BATCH_OFF + warp] = (float)b;
        }
    }

    const float R2 = 0.04f;
    int cnt = 0;
    for (int base = 0; base < NB; base += 32) {
        const int j = base + lane;
        float d2 = d2_exact(p[j * 3 + 0] - qx, p[j * 3 + 1] - qy, p[j * 3 + 2] - qz);
        const bool in = (d2 <= R2);
        const unsigned msk = __ballot_sync(0xffffffffu, in);
        if (in) {
            int r = cnt + __popc(msk & ((1u << lane) - 1u));
            if (r < KNB) g_nbr[warp * KNB + r] = j;
        }
        cnt += __popc(msk);
        if (cnt >= KNB) break;
    }
    if (lane == 0) g_cnt[warp] = cnt < KNB ? cnt : KNB;
}

// ================= 3) Conv via warp MMA (bf16x3), 512 threads =================
// Block = 2 centroids (M = 128 rows). 16 warps.
// GEMM1: warp tile 32x32.  GEMM2: warp tile 32x64.
#define OFF_A_HI   0
#define OFF_A_LO   34816
#define OFF_B_HI   69632
#define OFF_B_LO   139264
#define OFF_OMAX   208896
#define OFF_W1R    210944
#define CONV_SMEM  212480

__global__ __launch_bounds__(512, 1)
void conv_kernel(const float* __restrict__ pos, const float* __restrict__ W1,
                 const float* __restrict__ b2, const float* __restrict__ b3,
                 float* __restrict__ out) {
    extern __shared__ char sm[];
    const uint32_t sb = smem_u32(sm);
    __nv_bfloat16* Ahi = (__nv_bfloat16*)(sm + OFF_A_HI);
    __nv_bfloat16* Alo = (__nv_bfloat16*)(sm + OFF_A_LO);
    int*   omax = (int*)(sm + OFF_OMAX);
    float* w1r  = (float*)(sm + OFF_W1R);

    const int tid  = threadIdx.x;
    const int warp = tid >> 5;
    const int lane = tid & 31;
    const int g    = lane >> 2;
    const int tg   = lane & 3;
    const int c0   = blockIdx.x * 2;
    const int gp   = (c0 >> 10) * NB;

    if (tid < 512) omax[tid] = 0;
    if (tid < 128) {
        w1r[tid]       = __ldg(&W1[64 * H1 + tid]);
        w1r[128 + tid] = __ldg(&W1[65 * H1 + tid]);
        w1r[256 + tid] = __ldg(&W1[66 * H1 + tid]);
    }
    __syncthreads();

    // ---- phase 1: build A = h1 split (hi/lo bf16) ----
    {
        const int m    = tid >> 2;            // 0..127
        const int hf   = tid & 3;             // 32 cols each
        const int ci   = c0 + (m >> 6);
        const int slot = m & 63;
        const int cnt  = g_cnt[ci];
        const bool valid = slot < cnt;
        const int j = valid ? (g_nbr[ci * KNB + slot] + gp) : gp;
        const float rx = __ldg(&pos[j * 3 + 0]) - g_qpos[ci * 3 + 0];
        const float ry = __ldg(&pos[j * 3 + 1]) - g_qpos[ci * 3 + 1];
        const float rz = __ldg(&pos[j * 3 + 2]) - g_qpos[ci * 3 + 2];
        const float* xrow = g_xw1 + (size_t)j * H1;
#pragma unroll
        for (int c4 = hf * 32; c4 < hf * 32 + 32; c4 += 4) {
            const float4 xv = __ldg((const float4*)(xrow + c4));
            const float xe[4] = {xv.x, xv.y, xv.z, xv.w};
            __nv_bfloat16 hi[4], lo[4];
#pragma unroll
            for (int e = 0; e < 4; e++) {
                const int t = c4 + e;
                float v = xe[e];
                v = fmaf(rx, w1r[t], v);
                v = fmaf(ry, w1r[128 + t], v);
                v = fmaf(rz, w1r[256 + t], v);
                v = fmaxf(v, 0.0f);
                if (!valid) v = 0.0f;
                split_bf16(v, hi[e], lo[e]);
            }
            *(uint32_t*)(Ahi + m * LDA + c4)     = packbf(hi[0], hi[1]);
            *(uint32_t*)(Ahi + m * LDA + c4 + 2) = packbf(hi[2], hi[3]);
            *(uint32_t*)(Alo + m * LDA + c4)     = packbf(lo[0], lo[1]);
            *(uint32_t*)(Alo + m * LDA + c4 + 2) = packbf(lo[2], lo[3]);
        }
    }
    // copy W2T hi/lo images
    {
        const float4* s0 = (const float4*)g_w2t_hi;
        const float4* s1 = (const float4*)g_w2t_lo;
        float4* d0 = (float4*)(sm + OFF_B_HI);
        float4* d1 = (float4*)(sm + OFF_B_LO);
        for (int i = tid; i < (H2 * LDA * 2) / 16; i += 512) { d0[i] = s0[i]; d1[i] = s1[i]; }
    }
    __syncthreads();

    const uint32_t aAhi = sb + OFF_A_HI, aAlo = sb + OFF_A_LO;
    const uint32_t aBhi = sb + OFF_B_HI, aBlo = sb + OFF_B_LO;

    // ---- GEMM1: h2_pre[128x128] = A @ W2 (bf16x3); warp tile 32x32 ----
    float d1r[2][4][4] = {};
    {
        const int mw = (warp & 3) * 32;
        const int nw = (warp >> 2) * 32;
        for (int ks = 0; ks < 8; ks++) {
            const uint32_t colo = (uint32_t)(ks * 16 + (lane >> 4) * 8) * 2;
            uint32_t ah[2][4], al[2][4];
#pragma unroll
            for (int mf = 0; mf < 2; mf++) {
                const uint32_t ro = (uint32_t)(mw + mf * 16 + (lane & 15)) * (LDA * 2);
                ldmat4(ah[mf], aAhi + ro + colo);
                ldmat4(al[mf], aAlo + ro + colo);
            }
            uint32_t bh[4][2], bl[4][2];
#pragma unroll
            for (int np = 0; np < 2; np++) {
                const uint32_t ro = (uint32_t)(nw + np * 16 + (lane & 15)) * (LDA * 2);
                uint32_t r[4];
                ldmat4(r, aBhi + ro + colo);
                bh[2 * np][0] = r[0]; bh[2 * np][1] = r[2];
                bh[2 * np + 1][0] = r[1]; bh[2 * np + 1][1] = r[3];
                ldmat4(r, aBlo + ro + colo);
                bl[2 * np][0] = r[0]; bl[2 * np][1] = r[2];
                bl[2 * np + 1][0] = r[1]; bl[2 * np + 1][1] = r[3];
            }
#pragma unroll
            for (int mf = 0; mf < 2; mf++)
#pragma unroll
                for (int nf = 0; nf < 4; nf++) {
                    mma16816(d1r[mf][nf], ah[mf], bh[nf]);
                    mma16816(d1r[mf][nf], ah[mf], bl[nf]);
                    mma16816(d1r[mf][nf], al[mf], bh[nf]);
                }
        }
    }
    __syncthreads();

    // ---- epilogue 1: h2 = relu(D1 + b2) -> split back into A; copy W3T ----
    {
        const int mw = (warp & 3) * 32;
        const int nw = (warp >> 2) * 32;
#pragma unroll
        for (int mf = 0; mf < 2; mf++) {
            const int row0 = mw + mf * 16 + g;
#pragma unroll
            for (int nf = 0; nf < 4; nf++) {
                const int col = nw + nf * 8 + tg * 2;
                const float bb0 = __ldg(&b2[col]);
                const float bb1 = __ldg(&b2[col + 1]);
                const float v00 = fmaxf(d1r[mf][nf][0] + bb0, 0.0f);
                const float v01 = fmaxf(d1r[mf][nf][1] + bb1, 0.0f);
                const float v10 = fmaxf(d1r[mf][nf][2] + bb0, 0.0f);
                const float v11 = fmaxf(d1r[mf][nf][3] + bb1, 0.0f);
                __nv_bfloat16 h0, l0, h1b, l1b, h2b, l2b, h3b, l3b;
                split_bf16(v00, h0, l0);
                split_bf16(v01, h1b, l1b);
                split_bf16(v10, h2b, l2b);
                split_bf16(v11, h3b, l3b);
                *(uint32_t*)(Ahi + row0 * LDA + col)       = packbf(h0, h1b);
                *(uint32_t*)(Alo + row0 * LDA + col)       = packbf(l0, l1b);
                *(uint32_t*)(Ahi + (row0 + 8) * LDA + col) = packbf(h2b, h3b);
                *(uint32_t*)(Alo + (row0 + 8) * LDA + col) = packbf(l2b, l3b);
            }
        }
    }
    {
        const float4* s0 = (const float4*)g_w3t_hi;
        const float4* s1 = (const float4*)g_w3t_lo;
        float4* d0 = (float4*)(sm + OFF_B_HI);
        float4* d1 = (float4*)(sm + OFF_B_LO);
        for (int i = tid; i < (H3 * LDA * 2) / 16; i += 512) { d0[i] = s0[i]; d1[i] = s1[i]; }
    }
    __syncthreads();

    // ---- GEMM2 + fused masked max epilogue; warp tile 32x64 ----
    const int cnt0 = g_cnt[c0];
    const int cnt1 = g_cnt[c0 + 1];
    {
        const int m0 = (warp & 3) * 32;
        const int n0 = (warp >> 2) * 64;
        float d2r[2][8][4] = {};
        for (int ks = 0; ks < 8; ks++) {
            const uint32_t colo = (uint32_t)(ks * 16 + (lane >> 4) * 8) * 2;
            uint32_t ah[2][4], al[2][4];
#pragma unroll
            for (int mf = 0; mf < 2; mf++) {
                const uint32_t ro = (uint32_t)(m0 + mf * 16 + (lane & 15)) * (LDA * 2);
                ldmat4(ah[mf], aAhi + ro + colo);
                ldmat4(al[mf], aAlo + ro + colo);
            }
            uint32_t bh[8][2], bl[8][2];
#pragma unroll
            for (int np = 0; np < 4; np++) {
                const uint32_t ro = (uint32_t)(n0 + np * 16 + (lane & 15)) * (LDA * 2);
                uint32_t r[4];
                ldmat4(r, aBhi + ro + colo);
                bh[2 * np][0] = r[0]; bh[2 * np][1] = r[2];
                bh[2 * np + 1][0] = r[1]; bh[2 * np + 1][1] = r[3];
                ldmat4(r, aBlo + ro + colo);
                bl[2 * np][0] = r[0]; bl[2 * np][1] = r[2];
                bl[2 * np + 1][0] = r[1]; bl[2 * np + 1][1] = r[3];
            }
#pragma unroll
            for (int mf = 0; mf < 2; mf++)
#pragma unroll
                for (int nf = 0; nf < 8; nf++) {
                    mma16816(d2r[mf][nf], ah[mf], bh[nf]);
                    mma16816(d2r[mf][nf], ah[mf], bl[nf]);
                    mma16816(d2r[mf][nf], al[mf], bh[nf]);
                }
        }
        const int count = (m0 >= 64) ? cnt1 : cnt0;
        const int cbase = (m0 >= 64) ? 256 : 0;
        const int rr = (m0 & 32) + g;
        const bool v0 = rr < count;
        const bool v1 = rr + 8 < count;
        const bool v2 = rr + 16 < count;
        const bool v3 = rr + 24 < count;
#pragma unroll
        for (int nf = 0; nf < 8; nf++) {
            const int col = n0 + nf * 8 + tg * 2;
            const float bb0 = __ldg(&b3[col]);
            const float bb1 = __ldg(&b3[col + 1]);
            float mx0 = 0.0f, mx1 = 0.0f;
            if (v0) { mx0 = fmaxf(mx0, d2r[0][nf][0] + bb0); mx1 = fmaxf(mx1, d2r[0][nf][1] + bb1); }
            if (v1) { mx0 = fmaxf(mx0, d2r[0][nf][2] + bb0); mx1 = fmaxf(mx1, d2r[0][nf][3] + bb1); }
            if (v2) { mx0 = fmaxf(mx0, d2r[1][nf][0] + bb0); mx1 = fmaxf(mx1, d2r[1][nf][1] + bb1); }
            if (v3) { mx0 = fmaxf(mx0, d2r[1][nf][2] + bb0); mx1 = fmaxf(mx1, d2r[1][nf][3] + bb1); }
#pragma unroll
            for (int off = 4; off <= 16; off <<= 1) {
                mx0 = fmaxf(mx0, __shfl_xor_sync(0xffffffffu, mx0, off));
                mx1 = fmaxf(mx1, __shfl_xor_sync(0xffffffffu, mx1, off));
            }
            if (lane < 4) {
                atomicMax(&omax[cbase + col],     __float_as_int(mx0));
                atomicMax(&omax[cbase + col + 1], __float_as_int(mx1));
            }
        }
    }
    __syncthreads();

    if (tid < 512)
        out[(size_t)(c0 + (tid >> 8)) * H3 + (tid & 255)] = __int_as_float(omax[tid]);
}

// ================= launch =================
extern "C" void kernel_launch(void* const* d_in, const int* in_sizes, int n_in,
                              void* d_out, int out_size) {
    const float* x   = (const float*)d_in[0];
    const float* pos = (const float*)d_in[1];
    // d_in[2] = batch (int32), unused: clouds contiguous & equal-sized
    const float* W1  = (const float*)d_in[3];
    const float* b1  = (const float*)d_in[4];
    const float* W2  = (const float*)d_in[5];
    const float* b2  = (const float*)d_in[6];
    const float* W3  = (const float*)d_in[7];
    const float* b3  = (const float*)d_in[8];
    float* out = (float*)d_out;

    cudaFuncSetAttribute(conv_kernel, cudaFuncAttributeMaxDynamicSharedMemorySize, CONV_SMEM);

    fused_fps_prep<<<4 + NPREP, 256>>>(pos, x, W1, b1, W2, W3);
    radius_kernel<<<MTOT / 8, 256>>>(pos, out, (long long)out_size);
    conv_kernel<<<MTOT / 2, 512, CONV_SMEM>>>(pos, W1, b2, b3, out);
}

// round 7
// speedup vs baseline: 1.3658x; 1.2627x over previous
#include <cuda_runtime.h>
#include <cuda_bf16.h>
#include <math_constants.h>
#include <cstdint>

// ---------------- problem constants ----------------
#define BATCH_B   4
#define NB        4096
#define NPTS      (BATCH_B * NB)       // 16384
#define MBQ       1024                 // centroids per cloud
#define MTOT      (BATCH_B * MBQ)      // 4096
#define DIN       64
#define KNB       64
#define H1        128
#define H2        128
#define H3        256
#define LDA       136                  // padded A row stride (bf16 elems), 272B

#define POS_OFF      ((size_t)MTOT * H3)
#define POS_ELEMS    ((size_t)MTOT * 3)
#define BATCH_OFF    (POS_OFF + POS_ELEMS)
#define BATCH_ELEMS  ((size_t)MTOT)

// ---------------- device scratch ----------------
__device__ int   g_sel[MTOT];
__device__ float g_qpos[MTOT * 3];
__device__ int   g_nbr[MTOT * KNB];
__device__ int   g_cnt[MTOT];
__device__ float g_xw1[(size_t)NPTS * H1];
// MMA-fragment-order weight images: uint2 per (ktile*NT + ntile, lane)
// value.x = packbf(W[k][n], W[k+1][n]) with k = kt*16+(l&3)*2,   n = nt*8+(l>>2)
// value.y = same with k += 8
__device__ __align__(16) uint2 g_w2f_hi[8 * 16 * 32];    // 4096 uint2
__device__ __align__(16) uint2 g_w2f_lo[8 * 16 * 32];
__device__ __align__(16) uint2 g_w3f_hi[8 * 32 * 32];    // 8192 uint2
__device__ __align__(16) uint2 g_w3f_lo[8 * 32 * 32];

// exact mul-then-add (match XLA square->sum, no FMA contraction)
__device__ __forceinline__ float d2_exact(float dx, float dy, float dz) {
    return __fadd_rn(__fadd_rn(__fmul_rn(dx, dx), __fmul_rn(dy, dy)), __fmul_rn(dz, dz));
}

// ---- packed f32x2 helpers (FPS) ----
__device__ __forceinline__ unsigned long long pack2(float lo, float hi) {
    unsigned long long r;
    asm("mov.b64 %0, {%1, %2};" : "=l"(r) : "f"(lo), "f"(hi));
    return r;
}
__device__ __forceinline__ void unpack2(unsigned long long v, float& lo, float& hi) {
    asm("mov.b64 {%0, %1}, %2;" : "=f"(lo), "=f"(hi) : "l"(v));
}
__device__ __forceinline__ unsigned long long add2(unsigned long long a, unsigned long long b) {
    unsigned long long r;
    asm("add.rn.f32x2 %0, %1, %2;" : "=l"(r) : "l"(a), "l"(b));
    return r;
}
__device__ __forceinline__ unsigned long long mul2(unsigned long long a, unsigned long long b) {
    unsigned long long r;
    asm("mul.rn.f32x2 %0, %1, %2;" : "=l"(r) : "l"(a), "l"(b));
    return r;
}

// ---- mma/ldmatrix helpers (portable PTX) ----
__device__ __forceinline__ uint32_t smem_u32(const void* p) {
    uint32_t a;
    asm("{ .reg .u64 t; cvta.to.shared.u64 t, %1; cvt.u32.u64 %0, t; }" : "=r"(a) : "l"(p));
    return a;
}
__device__ __forceinline__ void ldmat4(uint32_t* r, uint32_t a) {
    asm volatile("ldmatrix.sync.aligned.m8n8.x4.shared.b16 {%0,%1,%2,%3}, [%4];"
                 : "=r"(r[0]), "=r"(r[1]), "=r"(r[2]), "=r"(r[3]) : "r"(a));
}
__device__ __forceinline__ void mma16816(float* d, const uint32_t* a, uint32_t b0, uint32_t b1) {
    asm volatile(
        "mma.sync.aligned.m16n8k16.row.col.f32.bf16.bf16.f32 "
        "{%0,%1,%2,%3}, {%4,%5,%6,%7}, {%8,%9}, {%0,%1,%2,%3};"
        : "+f"(d[0]), "+f"(d[1]), "+f"(d[2]), "+f"(d[3])
        : "r"(a[0]), "r"(a[1]), "r"(a[2]), "r"(a[3]), "r"(b0), "r"(b1));
}
__device__ __forceinline__ void split_bf16(float v, __nv_bfloat16& hi, __nv_bfloat16& lo) {
    hi = __float2bfloat16_rn(v);
    lo = __float2bfloat16_rn(v - __bfloat162float(hi));
}
__device__ __forceinline__ uint32_t packbf(__nv_bfloat16 a, __nv_bfloat16 b) {
    __nv_bfloat162 t;
    t.x = a; t.y = b;
    return *(uint32_t*)&t;
}

// ================= 1) fused: FPS (blocks 0-3) + xw1/W-frag prep (4..147) ====
#define FPT 16
#define NPREP 144
__global__ __launch_bounds__(256, 1)
void fused_fps_prep(const float* __restrict__ pos, const float* __restrict__ x,
                    const float* __restrict__ W1, const float* __restrict__ b1,
                    const float* __restrict__ W2, const float* __restrict__ W3) {
    __shared__ float spx[NB], spy[NB], spz[NB];
    __shared__ unsigned long long sled[2][8];

    if (blockIdx.x < 4) {
        // ---------------- FPS ----------------
        const int b    = blockIdx.x;
        const int tid  = threadIdx.x;
        const int lane = tid & 31;
        const int warp = tid >> 5;
        const float* p = pos + (size_t)b * NB * 3;

        unsigned long long ppx[FPT / 2], ppy[FPT / 2], ppz[FPT / 2];
        float dd[FPT];
        {
            float tx[FPT], ty[FPT], tz[FPT];
#pragma unroll
            for (int u = 0; u < FPT; u++) {
                const int j = u * 256 + tid;
                tx[u] = p[j * 3 + 0];
                ty[u] = p[j * 3 + 1];
                tz[u] = p[j * 3 + 2];
                spx[j] = tx[u]; spy[j] = ty[u]; spz[j] = tz[u];
                dd[u] = CUDART_INF_F;
            }
#pragma unroll
            for (int q = 0; q < FPT / 2; q++) {
                ppx[q] = pack2(tx[2 * q], tx[2 * q + 1]);
                ppy[q] = pack2(ty[2 * q], ty[2 * q + 1]);
                ppz[q] = pack2(tz[2 * q], tz[2 * q + 1]);
            }
        }
        if (tid == 0) g_sel[b * MBQ] = 0;
        __syncthreads();

        float cx = spx[0], cy = spy[0], cz = spz[0];

        for (int k = 1; k < MBQ; k++) {
            const unsigned long long ncx = pack2(-cx, -cx);
            const unsigned long long ncy = pack2(-cy, -cy);
            const unsigned long long ncz = pack2(-cz, -cz);
#pragma unroll
            for (int q = 0; q < FPT / 2; q++) {
                unsigned long long dx = add2(ppx[q], ncx);
                unsigned long long dy = add2(ppy[q], ncy);
                unsigned long long dz = add2(ppz[q], ncz);
                unsigned long long s  = add2(add2(mul2(dx, dx), mul2(dy, dy)), mul2(dz, dz));
                float d0, d1;
                unpack2(s, d0, d1);
                dd[2 * q]     = fminf(dd[2 * q], d0);
                dd[2 * q + 1] = fminf(dd[2 * q + 1], d1);
            }
            float tv[FPT]; int tu[FPT];
#pragma unroll
            for (int u = 0; u < FPT; u++) { tv[u] = dd[u]; tu[u] = u; }
#pragma unroll
            for (int step = 1; step < FPT; step <<= 1) {
#pragma unroll
                for (int u = 0; u < FPT; u += 2 * step) {
                    const bool take = tv[u + step] > tv[u];
                    tv[u] = take ? tv[u + step] : tv[u];
                    tu[u] = take ? tu[u + step] : tu[u];
                }
            }
            const int myidx = tu[0] * 256 + tid;
            const unsigned vb = __float_as_uint(tv[0]);
            const unsigned mx = __reduce_max_sync(0xffffffffu, vb);
            const unsigned cand = (vb == mx) ? (unsigned)myidx : 0xffffffffu;
            const unsigned imin = __reduce_min_sync(0xffffffffu, cand);

            const int par = k & 1;
            if (lane == 0)
                sled[par][warp] = ((unsigned long long)mx << 32) | (unsigned)(NB - 1 - imin);
            __syncthreads();

            unsigned long long m = sled[par][0];
#pragma unroll
            for (int w = 1; w < 8; w++) {
                unsigned long long o = sled[par][w];
                if (o > m) m = o;
            }
            const int widx = NB - 1 - (int)(unsigned)(m & 0xffffffffu);
            if (tid == 0) g_sel[b * MBQ + k] = widx;
            cx = spx[widx]; cy = spy[widx]; cz = spz[widx];
        }
    } else {
        // ---------------- prep: xw1 + weight fragment images ----------------
        const int pb  = blockIdx.x - 4;
        const int tid = threadIdx.x;
        const int t   = tid & 127;
        const int rh  = tid >> 7;

        for (int rp = pb; rp < NPTS / 2; rp += NPREP) {
            const int row = rp * 2 + rh;
            float acc = __ldg(&b1[t]);
            const float* xr = x + (size_t)row * DIN;
#pragma unroll 8
            for (int i = 0; i < DIN; i++)
                acc = fmaf(__ldg(&xr[i]), __ldg(&W1[i * H1 + t]), acc);
            g_xw1[(size_t)row * H1 + t] = acc;
        }

        // fragment images: w2 -> 8192 uint32 (4096 uint2), w3 -> 16384 uint32
        for (int idx = pb * 256 + tid; idx < 8192 + 16384; idx += NPREP * 256) {
            if (idx < 8192) {
                const int r  = idx & 1;
                const int l  = (idx >> 1) & 31;
                const int nt = (idx >> 6) & 15;
                const int kt = idx >> 10;
                const int k  = kt * 16 + (l & 3) * 2 + r * 8;
                const int n  = nt * 8 + (l >> 2);
                __nv_bfloat16 h0, l0, h1, l1;
                split_bf16(__ldg(&W2[k * H2 + n]), h0, l0);
                split_bf16(__ldg(&W2[(k + 1) * H2 + n]), h1, l1);
                ((uint32_t*)g_w2f_hi)[idx] = packbf(h0, h1);
                ((uint32_t*)g_w2f_lo)[idx] = packbf(l0, l1);
            } else {
                const int i2 = idx - 8192;
                const int r  = i2 & 1;
                const int l  = (i2 >> 1) & 31;
                const int nt = (i2 >> 6) & 31;
                const int kt = i2 >> 11;
                const int k  = kt * 16 + (l & 3) * 2 + r * 8;
                const int n  = nt * 8 + (l >> 2);
                __nv_bfloat16 h0, l0, h1, l1;
                split_bf16(__ldg(&W3[k * H3 + n]), h0, l0);
                split_bf16(__ldg(&W3[(k + 1) * H3 + n]), h1, l1);
                ((uint32_t*)g_w3f_hi)[i2] = packbf(h0, h1);
                ((uint32_t*)g_w3f_lo)[i2] = packbf(l0, l1);
            }
        }
    }
}

// ================= 2) Radius search (first K in index order) =================
__global__ __launch_bounds__(256)
void radius_kernel(const float* __restrict__ pos, float* __restrict__ out, long long out_size) {
    const int warp = (blockIdx.x * blockDim.x + threadIdx.x) >> 5;
    const int lane = threadIdx.x & 31;
    if (warp >= MTOT) return;
    const int b  = warp >> 10;
    const float* p = pos + (size_t)b * NB * 3;

    const int selIdx = g_sel[warp];
    const float qx = p[selIdx * 3 + 0];
    const float qy = p[selIdx * 3 + 1];
    const float qz = p[selIdx * 3 + 2];

    if (lane == 0) {
        g_qpos[warp * 3 + 0] = qx;
        g_qpos[warp * 3 + 1] = qy;
        g_qpos[warp * 3 + 2] = qz;
        if (out_size >= (long long)(POS_OFF + POS_ELEMS)) {
            out[POS_OFF + (size_t)warp * 3 + 0] = qx;
            out[POS_OFF + (size_t)warp * 3 + 1] = qy;
            out[POS_OFF + (size_t)warp * 3 + 2] = qz;
        }
        if (out_size >= (long long)(BATCH_OFF + BATCH_ELEMS)) {
            out[BATCH_OFF + warp] = (float)b;
        }
    }

    const float R2 = 0.04f;
    int cnt = 0;
    for (int base = 0; base < NB; base += 32) {
        const int j = base + lane;
        float d2 = d2_exact(p[j * 3 + 0] - qx, p[j * 3 + 1] - qy, p[j * 3 + 2] - qz);
        const bool in = (d2 <= R2);
        const unsigned msk = __ballot_sync(0xffffffffu, in);
        if (in) {
            int r = cnt + __popc(msk & ((1u << lane) - 1u));
            if (r < KNB) g_nbr[warp * KNB + r] = j;
        }
        cnt += __popc(msk);
        if (cnt >= KNB) break;
    }
    if (lane == 0) g_cnt[warp] = cnt < KNB ? cnt : KNB;
}

// ================= 3) Conv: smem = A only; B from gmem fragments =============
// Block = 2 centroids (M=128), 256 threads = 8 warps, 2 blocks/SM.
// Warp grid: wm = warp&1 (centroid / 64 rows), wn = warp>>1 (4 col groups).
#define OFF_A_HI   0
#define OFF_A_LO   34816
#define OFF_W1R    69632
#define CONV_SMEM  (69632 + 1536)

__global__ __launch_bounds__(256, 2)
void conv_kernel(const float* __restrict__ pos, const float* __restrict__ W1,
                 const float* __restrict__ b2, const float* __restrict__ b3,
                 float* __restrict__ out) {
    extern __shared__ char sm[];
    const uint32_t sb = smem_u32(sm);
    __nv_bfloat16* Ahi = (__nv_bfloat16*)(sm + OFF_A_HI);
    __nv_bfloat16* Alo = (__nv_bfloat16*)(sm + OFF_A_LO);
    float* w1r = (float*)(sm + OFF_W1R);

    const int tid  = threadIdx.x;
    const int warp = tid >> 5;
    const int lane = tid & 31;
    const int g    = lane >> 2;
    const int tg   = lane & 3;
    const int wm   = warp & 1;
    const int wn   = warp >> 1;
    const int c0   = blockIdx.x * 2;
    const int gp   = (c0 >> 10) * NB;

    if (tid < 128) {
        w1r[tid]       = __ldg(&W1[64 * H1 + tid]);
        w1r[128 + tid] = __ldg(&W1[65 * H1 + tid]);
        w1r[256 + tid] = __ldg(&W1[66 * H1 + tid]);
    }
    __syncthreads();

    // ---- phase 1: build A = h1 split (hi/lo bf16) ----
    {
        const int m    = tid >> 1;
        const int hf   = tid & 1;
        const int half = m >> 6;
        const int slot = m & 63;
        const int ci   = c0 + half;
        const int cnt  = g_cnt[ci];
        const bool valid = slot < cnt;
        const int j = valid ? (g_nbr[ci * KNB + slot] + gp) : gp;
        const float rx = __ldg(&pos[j * 3 + 0]) - g_qpos[ci * 3 + 0];
        const float ry = __ldg(&pos[j * 3 + 1]) - g_qpos[ci * 3 + 1];
        const float rz = __ldg(&pos[j * 3 + 2]) - g_qpos[ci * 3 + 2];
        const float* xrow = g_xw1 + (size_t)j * H1;
#pragma unroll 4
        for (int c4 = hf * 64; c4 < hf * 64 + 64; c4 += 4) {
            const float4 xv = __ldg((const float4*)(xrow + c4));
            const float xe[4] = {xv.x, xv.y, xv.z, xv.w};
            __nv_bfloat16 hi[4], lo[4];
#pragma unroll
            for (int e = 0; e < 4; e++) {
                const int t = c4 + e;
                float v = xe[e];
                v = fmaf(rx, w1r[t], v);
                v = fmaf(ry, w1r[128 + t], v);
                v = fmaf(rz, w1r[256 + t], v);
                v = fmaxf(v, 0.0f);
                if (!valid) v = 0.0f;
                split_bf16(v, hi[e], lo[e]);
            }
            *(uint32_t*)(Ahi + m * LDA + c4)     = packbf(hi[0], hi[1]);
            *(uint32_t*)(Ahi + m * LDA + c4 + 2) = packbf(hi[2], hi[3]);
            *(uint32_t*)(Alo + m * LDA + c4)     = packbf(lo[0], lo[1]);
            *(uint32_t*)(Alo + m * LDA + c4 + 2) = packbf(lo[2], lo[3]);
        }
    }
    __syncthreads();

    const uint32_t aAhi = sb + OFF_A_HI, aAlo = sb + OFF_A_LO;

    // ---- GEMM1: 128x128x128, warp tile 64m x 32n ----
    float d1r[4][4][4] = {};
    for (int ks = 0; ks < 8; ks++) {
        const uint32_t colo = (uint32_t)(ks * 16 + (lane >> 4) * 8) * 2;
        uint2 bh[4], bl[4];
#pragma unroll
        for (int nf = 0; nf < 4; nf++) {
            const int idx = (ks * 16 + (wn * 4 + nf)) * 32 + lane;
            bh[nf] = __ldg(&g_w2f_hi[idx]);
            bl[nf] = __ldg(&g_w2f_lo[idx]);
        }
#pragma unroll
        for (int mf = 0; mf < 4; mf++) {
            const uint32_t ro = (uint32_t)(wm * 64 + mf * 16 + (lane & 15)) * (LDA * 2);
            uint32_t ah[4], al[4];
            ldmat4(ah, aAhi + ro + colo);
            ldmat4(al, aAlo + ro + colo);
#pragma unroll
            for (int nf = 0; nf < 4; nf++) {
                mma16816(d1r[mf][nf], ah, bh[nf].x, bh[nf].y);
                mma16816(d1r[mf][nf], ah, bl[nf].x, bl[nf].y);
                mma16816(d1r[mf][nf], al, bh[nf].x, bh[nf].y);
            }
        }
    }
    __syncthreads();   // all reads of A(h1) done before overwrite

    // ---- epilogue 1: h2 = relu(D1 + b2) -> split back into A in place ----
    {
#pragma unroll
        for (int mf = 0; mf < 4; mf++) {
            const int row0 = wm * 64 + mf * 16 + g;
#pragma unroll
            for (int nf = 0; nf < 4; nf++) {
                const int col = wn * 32 + nf * 8 + tg * 2;
                const float bb0 = __ldg(&b2[col]);
                const float bb1 = __ldg(&b2[col + 1]);
                const float v00 = fmaxf(d1r[mf][nf][0] + bb0, 0.0f);
                const float v01 = fmaxf(d1r[mf][nf][1] + bb1, 0.0f);
                const float v10 = fmaxf(d1r[mf][nf][2] + bb0, 0.0f);
                const float v11 = fmaxf(d1r[mf][nf][3] + bb1, 0.0f);
                __nv_bfloat16 h0, l0, h1b, l1b, h2b, l2b, h3b, l3b;
                split_bf16(v00, h0, l0);
                split_bf16(v01, h1b, l1b);
                split_bf16(v10, h2b, l2b);
                split_bf16(v11, h3b, l3b);
                *(uint32_t*)(Ahi + row0 * LDA + col)       = packbf(h0, h1b);
                *(uint32_t*)(Alo + row0 * LDA + col)       = packbf(l0, l1b);
                *(uint32_t*)(Ahi + (row0 + 8) * LDA + col) = packbf(h2b, h3b);
                *(uint32_t*)(Alo + (row0 + 8) * LDA + col) = packbf(l2b, l3b);
            }
        }
    }
    __syncthreads();

    // ---- GEMM2 (128x256x128) + fused masked max; 2 reps of N=128 ----
    const int count = g_cnt[c0 + wm];
#pragma unroll
    for (int rep = 0; rep < 2; rep++) {
        float d2r[4][4][4] = {};
        for (int ks = 0; ks < 8; ks++) {
            const uint32_t colo = (uint32_t)(ks * 16 + (lane >> 4) * 8) * 2;
            uint2 bh[4], bl[4];
#pragma unroll
            for (int nf = 0; nf < 4; nf++) {
                const int idx = (ks * 32 + (rep * 16 + wn * 4 + nf)) * 32 + lane;
                bh[nf] = __ldg(&g_w3f_hi[idx]);
                bl[nf] = __ldg(&g_w3f_lo[idx]);
            }
#pragma unroll
            for (int mf = 0; mf < 4; mf++) {
                const uint32_t ro = (uint32_t)(wm * 64 + mf * 16 + (lane & 15)) * (LDA * 2);
                uint32_t ah[4], al[4];
                ldmat4(ah, aAhi + ro + colo);
                ldmat4(al, aAlo + ro + colo);
#pragma unroll
                for (int nf = 0; nf < 4; nf++) {
                    mma16816(d2r[mf][nf], ah, bh[nf].x, bh[nf].y);
                    mma16816(d2r[mf][nf], ah, bl[nf].x, bl[nf].y);
                    mma16816(d2r[mf][nf], al, bh[nf].x, bh[nf].y);
                }
            }
        }
        // masked max over this warp's 64 rows (= one full centroid)
#pragma unroll
        for (int nf = 0; nf < 4; nf++) {
            float mx0 = -CUDART_INF_F, mx1 = -CUDART_INF_F;
#pragma unroll
            for (int mf = 0; mf < 4; mf++) {
                const int r1 = mf * 16 + g;
                if (r1 < count)     { mx0 = fmaxf(mx0, d2r[mf][nf][0]); mx1 = fmaxf(mx1, d2r[mf][nf][1]); }
                if (r1 + 8 < count) { mx0 = fmaxf(mx0, d2r[mf][nf][2]); mx1 = fmaxf(mx1, d2r[mf][nf][3]); }
            }
#pragma unroll
            for (int off = 4; off <= 16; off <<= 1) {
                mx0 = fmaxf(mx0, __shfl_xor_sync(0xffffffffu, mx0, off));
                mx1 = fmaxf(mx1, __shfl_xor_sync(0xffffffffu, mx1, off));
            }
            if (g == 0) {
                const int col = rep * 128 + wn * 32 + nf * 8 + tg * 2;
                out[(size_t)(c0 + wm) * H3 + col]     = fmaxf(mx0 + __ldg(&b3[col]), 0.0f);
                out[(size_t)(c0 + wm) * H3 + col + 1] = fmaxf(mx1 + __ldg(&b3[col + 1]), 0.0f);
            }
        }
    }
}

// ================= launch =================
extern "C" void kernel_launch(void* const* d_in, const int* in_sizes, int n_in,
                              void* d_out, int out_size) {
    const float* x   = (const float*)d_in[0];
    const float* pos = (const float*)d_in[1];
    // d_in[2] = batch (int32), unused: clouds contiguous & equal-sized
    const float* W1  = (const float*)d_in[3];
    const float* b1  = (const float*)d_in[4];
    const float* W2  = (const float*)d_in[5];
    const float* b2  = (const float*)d_in[6];
    const float* W3  = (const float*)d_in[7];
    const float* b3  = (const float*)d_in[8];
    float* out = (float*)d_out;

    cudaFuncSetAttribute(conv_kernel, cudaFuncAttributeMaxDynamicSharedMemorySize, CONV_SMEM);

    fused_fps_prep<<<4 + NPREP, 256>>>(pos, x, W1, b1, W2, W3);
    radius_kernel<<<MTOT / 8, 256>>>(pos, out, (long long)out_size);
    conv_kernel<<<MTOT / 2, 256, CONV_SMEM>>>(pos, W1, b2, b3, out);
}